// round 16
// baseline (speedup 1.0000x reference)
#include <cuda_runtime.h>
#include <cstdint>

#define KSEG 160
#define BATCH 1024

// ---------------- device scratch (no allocation allowed) ----------------
__device__ __align__(16) float g_GIa[(size_t)BATCH * KSEG * 36];  // gates: r,z pre-scaled x0.5; n raw
__device__ __align__(16) float g_PW[KSEG * 36];                   // pe@Wih^T per k (same scaling)
__device__ __align__(16) float g_Mp[4 * KSEG * 144];              // decmat partials
__device__ __align__(16) float g_cp[4 * KSEG * 12];               // dec bias partials
__device__ __align__(16) float g_out[(size_t)BATCH * KSEG * 12];  // GRU2 outputs, [b][k][u]

__device__ __forceinline__ float tanhf_(float x) { float y; asm("tanh.approx.f32 %0, %1;" : "=f"(y) : "f"(x)); return y; }

// ---------------- fused prep + decmat_part ----------------
// grid (160, 12) x 160 threads:
//   blockIdx.y < 8  : prep for (k = blockIdx.x, batch slice blockIdx.y), threads 0..127
//   blockIdx.y >= 8 : decmat partial for (k = blockIdx.x, part = blockIdx.y - 8)
__global__ void __launch_bounds__(160) fused_prep_kernel(
    const float* __restrict__ x, const float* __restrict__ encW,
    const float* __restrict__ encb, const float* __restrict__ Wih,
    const float* __restrict__ bih, const float* __restrict__ bhh,
    const float* __restrict__ W1, const float* __restrict__ b1,
    const float* __restrict__ W2, const float* __restrict__ b2)
{
    const int k = blockIdx.x;
    const int tid = threadIdx.x;

    if (blockIdx.y >= 8) {
        // ---- decmat partial: h-slice of 256, 8 accumulators ----
        const int part = blockIdx.y - 8;
        const int hbase = part * 256;
        const int t = tid;
        if (t < 144) {
            const int o = t / 12, d = t % 12;
            const float* w1 = W1 + ((size_t)k * 12 + d) * 1024 + hbase;
            const float* w2 = W2 + (size_t)k * 12288 + (size_t)hbase * 12 + o;
            float a[8];
#pragma unroll
            for (int j = 0; j < 8; j++) a[j] = 0.f;
#pragma unroll 2
            for (int h = 0; h < 256; h += 8) {
#pragma unroll
                for (int j = 0; j < 8; j++)
                    a[j] = fmaf(w1[h + j], w2[(size_t)(h + j) * 12], a[j]);
            }
            g_Mp[((size_t)part * KSEG + k) * 144 + t] =
                ((a[0] + a[1]) + (a[2] + a[3])) + ((a[4] + a[5]) + (a[6] + a[7]));
        } else if (t < 156) {
            const int o = t - 144;
            const float* bb = b1 + (size_t)k * 1024 + hbase;
            const float* w2 = W2 + (size_t)k * 12288 + (size_t)hbase * 12 + o;
            float a[8];
#pragma unroll
            for (int j = 0; j < 8; j++) a[j] = 0.f;
            a[0] = (part == 0) ? b2[k * 12 + o] : 0.f;
#pragma unroll 2
            for (int h = 0; h < 256; h += 8) {
#pragma unroll
                for (int j = 0; j < 8; j++)
                    a[j] = fmaf(bb[h + j], w2[(size_t)(h + j) * 12], a[j]);
            }
            g_cp[((size_t)part * KSEG + k) * 12 + o] =
                ((a[0] + a[1]) + (a[2] + a[3])) + ((a[4] + a[5]) + (a[6] + a[7]));
        }
        return;
    }

    // ---- prep: encoder + pre-scaled GRU1 gates + per-k PE table ----
    __shared__ float s_encW[144], s_encb[12], s_Wih[432], s_base[36], s_pe[12];

    for (int i = tid; i < 144; i += 160) s_encW[i] = encW[k * 144 + i];
    if (tid < 12) s_encb[tid] = encb[k * 12 + tid];
    for (int i = tid; i < 432; i += 160) s_Wih[i] = Wih[i];
    if (tid < 36) s_base[tid] = bih[tid] + (tid < 24 ? bhh[tid] : 0.0f);
    if (tid < 12) {
        // pos_enc (sinusoidal, d=12) + channel_enc (= sin(k) broadcast over dims)
        float pos = (float)k;
        float div = expf((float)(tid & ~1) * (-9.210340371976184f / 12.0f));
        float ang = pos * div;
        float v = (tid & 1) ? cosf(ang) : sinf(ang);
        s_pe[tid] = v + sinf(pos);
    }
    __syncthreads();

    // per-k PE gate contribution (pre-scaled), written once
    if (blockIdx.y == 0 && tid < 36) {
        float acc = 0.0f;
#pragma unroll
        for (int i = 0; i < 12; i++) acc = fmaf(s_pe[i], s_Wih[tid * 12 + i], acc);
        g_PW[k * 36 + tid] = ((tid < 24) ? 0.5f : 1.0f) * acc;
    }

    if (tid >= 128) return;
    const int b = blockIdx.y * 128 + tid;

    // encoder: xs = relu(xb @ encW[k] + encb[k])
    const float4* xp = reinterpret_cast<const float4*>(x + (size_t)b * 1920 + k * 12);
    float4 v0 = xp[0], v1 = xp[1], v2 = xp[2];
    float xb[12] = {v0.x, v0.y, v0.z, v0.w, v1.x, v1.y, v1.z, v1.w, v2.x, v2.y, v2.z, v2.w};
    float xs[12];
#pragma unroll
    for (int o = 0; o < 12; o++) {
        float a = s_encb[o];
#pragma unroll
        for (int i = 0; i < 12; i++) a = fmaf(xb[i], s_encW[i * 12 + o], a);
        xs[o] = fmaxf(a, 0.0f);
    }

    // GRU1 gates only (PE handled via g_PW in phase2), 4 at a time
    float4* oa = reinterpret_cast<float4*>(g_GIa + ((size_t)b * KSEG + k) * 36);
#pragma unroll 1
    for (int q = 0; q < 9; q++) {
        float aa[4];
#pragma unroll
        for (int j = 0; j < 4; j++) {
            const int g = 4 * q + j;
            float sa = s_base[g];
#pragma unroll
            for (int i = 0; i < 12; i++) sa = fmaf(xs[i], s_Wih[g * 12 + i], sa);
            aa[j] = sa;
        }
        const float scl = (q < 6) ? 0.5f : 1.0f;
        oa[q] = make_float4(scl * aa[0], scl * aa[1], scl * aa[2], scl * aa[3]);
    }
}

// ---------------- sequential GRU: 2 batches/warp, width-16 SHFL broadcast ----------------
#define DOTT(OUT, W, INIT) do { \
    float a0_ = fmaf(h1, W##1, h0 * W##0); \
    float a1_ = fmaf(h3, W##3, h2 * W##2); \
    float a2_ = fmaf(h5, W##5, h4 * W##4); \
    float a3_ = fmaf(h7, W##7, h6 * W##6); \
    float a4_ = fmaf(h9, W##9, h8 * W##8); \
    float a5_ = fmaf(h11, W##11, h10 * W##10); \
    OUT = ((a0_ + a1_) + (a2_ + a3_)) + ((a4_ + a5_) + (INIT)); \
} while (0)

// sigma(x) = 0.5 + 0.5*tanh(x/2); r,z gates & weights pre-scaled by 0.5; n raw.
// SHFL width 16: each 16-lane half broadcasts its own batch's h.
#define GRU_PHASE(PH2) do { \
    float qr[8], qz[8], qn[8]; \
    _Pragma("unroll") \
    for (int s_ = 0; s_ < 8; s_++) { \
        qr[s_] = p_[s_ * 36];       qz[s_] = p_[s_ * 36 + 12];       qn[s_] = p_[s_ * 36 + 24]; \
        if (PH2) { qr[s_] += pw_[s_ * 36]; qz[s_] += pw_[s_ * 36 + 12]; qn[s_] += pw_[s_ * 36 + 24]; } \
    } \
    _Pragma("unroll 8") \
    for (int k = 0; k < 160; k++) { \
        const int sl_ = k & 7; \
        float cgr = qr[sl_], cgz = qz[sl_], cgn = qn[sl_]; \
        const int kp_ = (k + 8 < 160) ? (k + 8) : 159;  /* clamped refill; unused past end */ \
        float rr_ = p_[kp_ * 36], rz_ = p_[kp_ * 36 + 12], rn_ = p_[kp_ * 36 + 24]; \
        if (PH2) { rr_ += pw_[kp_ * 36]; rz_ += pw_[kp_ * 36 + 12]; rn_ += pw_[kp_ * 36 + 24]; } \
        qr[sl_] = rr_; qz[sl_] = rz_; qn[sl_] = rn_; \
        float tr_, tz_, tn_; \
        DOTT(tr_, wr, cgr); \
        DOTT(tz_, wz, cgz); \
        DOTT(tn_, wn, bnp); \
        float r_ = fmaf(0.5f, tanhf_(tr_), 0.5f); \
        float z_ = fmaf(0.5f, tanhf_(tz_), 0.5f); \
        float n_ = tanhf_(fmaf(r_, tn_, cgn)); \
        float hnew_ = fmaf(z_, hprev - n_, n_); \
        hprev = hnew_; \
        h0  = __shfl_sync(0xffffffffu, hnew_, 0, 16); \
        h1  = __shfl_sync(0xffffffffu, hnew_, 1, 16); \
        h2  = __shfl_sync(0xffffffffu, hnew_, 2, 16); \
        h3  = __shfl_sync(0xffffffffu, hnew_, 3, 16); \
        h4  = __shfl_sync(0xffffffffu, hnew_, 4, 16); \
        h5  = __shfl_sync(0xffffffffu, hnew_, 5, 16); \
        h6  = __shfl_sync(0xffffffffu, hnew_, 6, 16); \
        h7  = __shfl_sync(0xffffffffu, hnew_, 7, 16); \
        h8  = __shfl_sync(0xffffffffu, hnew_, 8, 16); \
        h9  = __shfl_sync(0xffffffffu, hnew_, 9, 16); \
        h10 = __shfl_sync(0xffffffffu, hnew_, 10, 16); \
        h11 = __shfl_sync(0xffffffffu, hnew_, 11, 16); \
        if (PH2 && hu < 12) outp[(size_t)k * 12 + hu] = hnew_; \
    } \
} while (0)

__global__ void __launch_bounds__(128) gru_kernel(const float* __restrict__ Whh,
                                                  const float* __restrict__ bhh)
{
    const int warp = threadIdx.x >> 5;
    const int lane = threadIdx.x & 31;
    const int half = lane >> 4;                    // 0 = batch A, 1 = batch B
    const int hu = lane & 15;                      // unit index within half (0..15; 12..15 dup)
    const int b = (blockIdx.x * 4 + warp) * 2 + half;  // 128 blocks x 4 warps x 2 = 1024
    const int u = hu % 12;

    const float* wrp = Whh + u * 12;
    const float* wzp = Whh + (u + 12) * 12;
    const float* wnp = Whh + (u + 24) * 12;
    float wr0 = 0.5f * wrp[0], wr1 = 0.5f * wrp[1], wr2 = 0.5f * wrp[2], wr3 = 0.5f * wrp[3];
    float wr4 = 0.5f * wrp[4], wr5 = 0.5f * wrp[5], wr6 = 0.5f * wrp[6], wr7 = 0.5f * wrp[7];
    float wr8 = 0.5f * wrp[8], wr9 = 0.5f * wrp[9], wr10 = 0.5f * wrp[10], wr11 = 0.5f * wrp[11];
    float wz0 = 0.5f * wzp[0], wz1 = 0.5f * wzp[1], wz2 = 0.5f * wzp[2], wz3 = 0.5f * wzp[3];
    float wz4 = 0.5f * wzp[4], wz5 = 0.5f * wzp[5], wz6 = 0.5f * wzp[6], wz7 = 0.5f * wzp[7];
    float wz8 = 0.5f * wzp[8], wz9 = 0.5f * wzp[9], wz10 = 0.5f * wzp[10], wz11 = 0.5f * wzp[11];
    float wn0 = wnp[0], wn1 = wnp[1], wn2 = wnp[2], wn3 = wnp[3];
    float wn4 = wnp[4], wn5 = wnp[5], wn6 = wnp[6], wn7 = wnp[7];
    float wn8 = wnp[8], wn9 = wnp[9], wn10 = wnp[10], wn11 = wnp[11];
    const float bnp = bhh[24 + u];

    float h0 = 0.f, h1 = 0.f, h2 = 0.f, h3 = 0.f, h4 = 0.f, h5 = 0.f;
    float h6 = 0.f, h7 = 0.f, h8 = 0.f, h9 = 0.f, h10 = 0.f, h11 = 0.f;
    float hprev = 0.f;

    const float* p_ = g_GIa + (size_t)b * KSEG * 36 + u;
    const float* pw_ = g_PW + u;
    float* outp = g_out + (size_t)b * KSEG * 12;

    GRU_PHASE(false);  // GRU1: only h_T survives
    GRU_PHASE(true);   // GRU2: gates = GIa + PW[k], stores raw h
}

// ---------------- decoder apply: res = out @ M[k] + c[k]; reduces partials in-block ----------------
__global__ void __launch_bounds__(128) dec_kernel(float* __restrict__ out)
{
    __shared__ float sM[144], sc[12];
    const int k = blockIdx.x, tid = threadIdx.x;
    for (int i = tid; i < 144; i += 128) {
        float s = ((g_Mp[((size_t)0 * KSEG + k) * 144 + i] + g_Mp[((size_t)1 * KSEG + k) * 144 + i])
                 + (g_Mp[((size_t)2 * KSEG + k) * 144 + i] + g_Mp[((size_t)3 * KSEG + k) * 144 + i]));
        sM[i] = s;
    }
    if (tid < 12) {
        sc[tid] = ((g_cp[((size_t)0 * KSEG + k) * 12 + tid] + g_cp[((size_t)1 * KSEG + k) * 12 + tid])
                 + (g_cp[((size_t)2 * KSEG + k) * 12 + tid] + g_cp[((size_t)3 * KSEG + k) * 12 + tid]));
    }
    __syncthreads();

    const int b = blockIdx.y * 128 + tid;
    const float4* hp = reinterpret_cast<const float4*>(g_out + ((size_t)b * KSEG + k) * 12);
    float4 a0 = hp[0], a1 = hp[1], a2 = hp[2];
    float hv[12] = {a0.x, a0.y, a0.z, a0.w, a1.x, a1.y, a1.z, a1.w, a2.x, a2.y, a2.z, a2.w};
    float ov[12];
#pragma unroll
    for (int o = 0; o < 12; o++) {
        float acc = sc[o];
#pragma unroll
        for (int d = 0; d < 12; d++) acc = fmaf(hv[d], sM[o * 12 + d], acc);
        ov[o] = acc;
    }
    float4* op = reinterpret_cast<float4*>(out + (size_t)b * 1920 + k * 12);
    op[0] = make_float4(ov[0], ov[1], ov[2], ov[3]);
    op[1] = make_float4(ov[4], ov[5], ov[6], ov[7]);
    op[2] = make_float4(ov[8], ov[9], ov[10], ov[11]);
}

// ---------------- launch ----------------
extern "C" void kernel_launch(void* const* d_in, const int* in_sizes, int n_in,
                              void* d_out, int out_size)
{
    (void)in_sizes; (void)n_in; (void)out_size;
    const float* x    = (const float*)d_in[0];
    const float* encW = (const float*)d_in[1];
    const float* encb = (const float*)d_in[2];
    const float* Wih  = (const float*)d_in[3];
    const float* Whh  = (const float*)d_in[4];
    const float* bih  = (const float*)d_in[5];
    const float* bhh  = (const float*)d_in[6];
    const float* W1   = (const float*)d_in[7];
    const float* b1   = (const float*)d_in[8];
    const float* W2   = (const float*)d_in[9];
    const float* b2   = (const float*)d_in[10];
    float* out = (float*)d_out;

    fused_prep_kernel<<<dim3(160, 12), 160>>>(x, encW, encb, Wih, bih, bhh,
                                              W1, b1, W2, b2);   // launch 1: prep + decmat parts
    gru_kernel<<<128, 128>>>(Whh, bhh);                          // launch 2
    dec_kernel<<<dim3(160, 8), 128>>>(out);                     // launch 3
}